// round 15
// baseline (speedup 1.0000x reference)
#include <cuda_runtime.h>
#include <cuda_bf16.h>

#define BB 4
#define MM 2048
#define HH 16
#define NJ 10
#define SCALE   0.3535533905932738f    // (128//16)^-0.5
#define INV2048 4.8828125e-4f          // 1/2048 (exact)

__constant__ float c_F[NJ] = {
    1.0f, 1.0f, 0.5f, 0.16666666666666666f,
    0.041666666666666664f, 0.008333333333333333f,
    0.001388888888888889f, 1.984126984126984e-4f,
    2.48015873015873e-5f,  2.7557319223985893e-6f
};

// cross-block LN state (zero-init; self-resetting every run)
__device__ float2 g_part[BB * HH];
__device__ int    g_cnt[BB];
__device__ int    g_done[BB];

__global__ void __launch_bounds__(512, 1)
k_fused(const float* __restrict__ query, const float* __restrict__ key_,
        const float* __restrict__ value, const float* __restrict__ wq,
        const float* __restrict__ wk,    const float* __restrict__ wv,
        const float* __restrict__ wf,    const float* __restrict__ lnw,
        const float* __restrict__ lnb,   float* __restrict__ out) {
    const int b    = blockIdx.x >> 4;
    const int h    = blockIdx.x & 15;
    const int tid  = threadIdx.x;
    const int lane = tid & 31;
    const int warp = tid >> 5;

    // ovl: phase1 = staged weights Sq/Sf/Sk/Sv (4 x 2112, pad-132 rows);
    //      phase2 = iv[t*132+p] (2112) reuses the front.
    __shared__ float ovl[8448];
    __shared__ float AshT[256];     // SCALE*A(s,t) at [t*16+s]
    __shared__ float GtsT[256];     // G(t,s)      at [t*16+s]
    __shared__ float Qs[128], Ks[128], Vs[128];
    __shared__ float SAt[256];      // [t*16+j], j>=NJ zeroed
    __shared__ float AGj[256];      // [j*16+t], j<NJ used
    __shared__ float FQ[16];        // F_j*QM_j, j>=NJ zeroed
    __shared__ float Psh[256];      // [j*16+t] : U[j][t]*AG[j][t]
    __shared__ float Wfs[16];
    __shared__ float redS[4], redS2[4];
    __shared__ float mu_s, rs_s;

    float* Sq = ovl;
    float* Sf = ovl + 2112;
    float* Sk = ovl + 4224;
    float* Sv = ovl + 6336;
    float* iv = ovl;                // overlay after dots

    // ---- per-thread global inputs (issue LDGs early) ----
    float qv = 0.f, kval = 0.f, vval = 0.f, lwv = 0.f, lbv = 0.f;
    if (tid < 128) {
        int gi = b * MM + h * 128 + tid;
        qv = query[gi]; kval = key_[gi]; vval = value[gi];
        lwv = lnw[h * 128 + tid]; lbv = lnb[h * 128 + tid];
    }

    // ---- stage weights: padded rows [st*132 + d], 1 f4 each ----
    {
        int st = tid >> 5, off = tid & 31;
        int fi = st * 33 + off;
        ((float4*)Sq)[fi] = ((const float4*)wq)[tid];
        ((float4*)Sf)[fi] = ((const float4*)wf)[tid];
        ((float4*)Sk)[fi] = ((const float4*)wk)[tid];
        ((float4*)Sv)[fi] = ((const float4*)wv)[tid];
    }
    if (tid < 256) SAt[tid] = 0.f;
    if (tid < 16)  FQ[tid] = 0.f;
    if (tid < 128) { Qs[tid] = qv; Ks[tid] = kval; Vs[tid] = vval; }
    __syncthreads();

    // ---- dual GEMM 16x16x128: warps 0-7 -> A, warps 8-15 -> G ----
    {
        int isG  = warp >> 3;
        int sblk = (warp >> 2) & 1, tblk = warp & 3;
        int s = sblk * 8 + (lane >> 2);
        int t = tblk * 4 + (lane & 3);
        const float4* X = (const float4*)((isG ? Sf : Sq) + s * 132);
        const float4* Y = (const float4*)((isG ? Sv : Sk) + t * 132);
        float ax = 0.f, ay = 0.f, az = 0.f, aw = 0.f;
#pragma unroll
        for (int i = 0; i < 32; i++) {
            float4 x = X[i], y = Y[i];
            ax = fmaf(x.x, y.x, ax);
            ay = fmaf(x.y, y.y, ay);
            az = fmaf(x.z, y.z, az);
            aw = fmaf(x.w, y.w, aw);
        }
        float a = (ax + ay) + (az + aw);
        if (isG) GtsT[t * 16 + s] = a;
        else     AshT[t * 16 + s] = SCALE * a;
    }
    __syncthreads();

    // ---- SA/AG (warps 0-7): batched — partials first, ONE pipelined butterfly ----
    if (warp < 8) {
        int t = warp * 2 + (lane >> 4);
        int s = lane & 15;
        float a = AshT[t * 16 + s];
        float g = GtsT[t * 16 + s];
        float sa[NJ], ag[NJ];
        float pw = 1.f;
#pragma unroll
        for (int j = 0; j < NJ; j++) { sa[j] = pw; ag[j] = pw * g; pw *= a; }
#pragma unroll
        for (int o = 1; o < 16; o <<= 1) {
#pragma unroll
            for (int j = 0; j < NJ; j++) {
                sa[j] += __shfl_xor_sync(0xffffffffu, sa[j], o);
                ag[j] += __shfl_xor_sync(0xffffffffu, ag[j], o);
            }
        }
        int jj = lane & 15;
#pragma unroll
        for (int j = 0; j < NJ; j++)
            if (jj == j) { SAt[t * 16 + j] = sa[j]; AGj[j * 16 + t] = ag[j]; }
    } else if (warp == 8) {
        // ---- FQ[j] = F_j * QM_j (batched identically) ----
        float4 q4 = ((const float4*)Qs)[lane];
        float qm[NJ];
        float px = 1.f, py = 1.f, pz = 1.f, pw4 = 1.f;
#pragma unroll
        for (int j = 0; j < NJ; j++) {
            qm[j] = (px + py) + (pz + pw4);
            px *= q4.x; py *= q4.y; pz *= q4.z; pw4 *= q4.w;
        }
#pragma unroll
        for (int o = 1; o < 32; o <<= 1)
#pragma unroll
            for (int j = 0; j < NJ; j++)
                qm[j] += __shfl_xor_sync(0xffffffffu, qm[j], o);
#pragma unroll
        for (int j = 0; j < NJ; j++)
            if (lane == j) FQ[j] = c_F[j] * qm[j];
    }
    __syncthreads();

    // ---- Z Horner + series reciprocal -> iv[t][p] = V_p * 2048/Z(p,t) ----
    {
        int p = tid & 127, tq = tid >> 7;
        float k = Ks[p], v = Vs[p];
        float4 f0 = ((const float4*)FQ)[0];
        float4 f1 = ((const float4*)FQ)[1];
        float4 f2 = ((const float4*)FQ)[2];
#pragma unroll
        for (int tt = 0; tt < 4; tt++) {
            int t = tq * 4 + tt;
            const float4* s4 = (const float4*)(SAt + t * 16);
            float4 s0 = s4[0], s1 = s4[1], s2 = s4[2];
            float z = f2.w * s2.w;                 // zero (padded)
            z = fmaf(z, k, f2.z * s2.z);
            z = fmaf(z, k, f2.y * s2.y);
            z = fmaf(z, k, f2.x * s2.x);
            z = fmaf(z, k, f1.w * s1.w);
            z = fmaf(z, k, f1.z * s1.z);
            z = fmaf(z, k, f1.y * s1.y);
            z = fmaf(z, k, f1.x * s1.x);
            z = fmaf(z, k, f0.w * s0.w);
            z = fmaf(z, k, f0.z * s0.z);
            z = fmaf(z, k, f0.y * s0.y);
            z = fmaf(z, k, f0.x * s0.x);           // c0 = 2048 exactly
            float e = fmaf(z, INV2048, -1.0f);     // eps, |eps| << 1
            float r = fmaf(-e, 1.0f, 1.0f);        // 1/(1+eps), err eps^7
            r = fmaf(-e, r, 1.0f);
            r = fmaf(-e, r, 1.0f);
            r = fmaf(-e, r, 1.0f);
            r = fmaf(-e, r, 1.0f);
            r = fmaf(-e, r, 1.0f);
            iv[t * 132 + p] = v * r;               // 1/2048 folded into Wf
        }
    }
    __syncthreads();

    // ---- U phase (warp = t): batched partials + ONE pipelined butterfly ----
    {
        int t = warp;
        float4 iv4 = ((const float4*)(iv + t * 132))[lane];
        float4 k4  = ((const float4*)Ks)[lane];
        float u[NJ];
        float kx = 1.f, ky = 1.f, kz = 1.f, kw = 1.f;
#pragma unroll
        for (int j = 0; j < NJ; j++) {
            u[j] = fmaf(kx, iv4.x, fmaf(ky, iv4.y, fmaf(kz, iv4.z, kw * iv4.w)));
            kx *= k4.x; ky *= k4.y; kz *= k4.z; kw *= k4.w;
        }
#pragma unroll
        for (int o = 1; o < 32; o <<= 1)
#pragma unroll
            for (int j = 0; j < NJ; j++)
                u[j] += __shfl_xor_sync(0xffffffffu, u[j], o);
#pragma unroll
        for (int j = 0; j < NJ; j++)
            if (lane == j) Psh[j * 16 + t] = u[j] * AGj[j * 16 + t];
    }
    __syncthreads();

    // ---- Wf[j] = F_j/2048 * sum_t Psh[j][t] ----
    if (tid < NJ) {
        const float4* p4 = (const float4*)(Psh + tid * 16);
        float4 a = p4[0], c = p4[1], d = p4[2], e = p4[3];
        float s = ((a.x + a.y) + (a.z + a.w)) + ((c.x + c.y) + (c.z + c.w))
                + ((d.x + d.y) + (d.z + d.w)) + ((e.x + e.y) + (e.z + e.w));
        Wfs[tid] = c_F[tid] * INV2048 * s;
    }
    __syncthreads();

    // ---- y = q + sum_j Wf[j] q^j ; per-block LN partials ----
    float yv = 0.f;
    if (tid < 128) {
        float val = Wfs[NJ - 1];
#pragma unroll
        for (int j = NJ - 2; j >= 0; j--) val = fmaf(val, qv, Wfs[j]);
        yv = qv + val;
        float s1 = yv, s2 = yv * yv;
#pragma unroll
        for (int o = 16; o; o >>= 1) {
            s1 += __shfl_down_sync(0xffffffffu, s1, o);
            s2 += __shfl_down_sync(0xffffffffu, s2, o);
        }
        if (lane == 0) { redS[warp] = s1; redS2[warp] = s2; }
    }
    __syncthreads();

    // ---- publish partials, spin until all 16 heads arrived ----
    if (tid == 0) {
        float ps  = (redS[0]  + redS[1])  + (redS[2]  + redS[3]);
        float ps2 = (redS2[0] + redS2[1]) + (redS2[2] + redS2[3]);
        g_part[b * HH + h] = make_float2(ps, ps2);
        __threadfence();
        atomicAdd(&g_cnt[b], 1);
        while (((volatile int*)g_cnt)[b] < HH) { }
        __threadfence();
    }
    __syncthreads();

    // ---- every block computes mu/rs from the 16 partials ----
    if (warp == 0) {
        float a = 0.f, c = 0.f;
        if (lane < HH) {
            float2 pp = __ldcg(&g_part[b * HH + lane]);
            a = pp.x; c = pp.y;
        }
#pragma unroll
        for (int o = 8; o; o >>= 1) {
            a += __shfl_xor_sync(0xffffffffu, a, o);
            c += __shfl_xor_sync(0xffffffffu, c, o);
        }
        if (lane == 0) {
            float mu  = a * (1.0f / MM);
            float var = c * (1.0f / MM) - mu * mu;
            mu_s = mu;
            rs_s = rsqrtf(var + 1e-5f);
        }
    }
    __syncthreads();
    if (tid < 128)
        out[b * MM + h * 128 + tid] = (yv - mu_s) * rs_s * lwv + lbv;

    // ---- reset counters for next graph replay ----
    if (tid == 0) {
        int old = atomicAdd(&g_done[b], 1);
        if (old == HH - 1) { g_cnt[b] = 0; g_done[b] = 0; }
    }
}

extern "C" void kernel_launch(void* const* d_in, const int* in_sizes, int n_in,
                              void* d_out, int out_size) {
    const float* query = (const float*)d_in[0];
    const float* key_  = (const float*)d_in[1];
    const float* value = (const float*)d_in[2];
    const float* wq    = (const float*)d_in[3];
    const float* wk    = (const float*)d_in[4];
    const float* wv    = (const float*)d_in[5];
    const float* wf    = (const float*)d_in[6];
    const float* lw    = (const float*)d_in[7];
    const float* lb    = (const float*)d_in[8];
    float* out = (float*)d_out;

    k_fused<<<BB * HH, 512>>>(query, key_, value, wq, wk, wv, wf, lw, lb, out);
}

// round 16
// speedup vs baseline: 1.1895x; 1.1895x over previous
#include <cuda_runtime.h>
#include <cuda_bf16.h>

#define BB 4
#define MM 2048
#define HH 16
#define NJ 8
#define SCALE   0.3535533905932738f    // (128//16)^-0.5
#define INV2048 4.8828125e-4f          // 1/2048 (exact)

__constant__ float c_F[NJ] = {
    1.0f, 1.0f, 0.5f, 0.16666666666666666f,
    0.041666666666666664f, 0.008333333333333333f,
    0.001388888888888889f, 1.984126984126984e-4f
};

typedef unsigned long long u64;
__device__ __forceinline__ u64 pk2(float lo, float hi) {
    u64 r; asm("mov.b64 %0,{%1,%2};" : "=l"(r) : "f"(lo), "f"(hi)); return r;
}
__device__ __forceinline__ void upk2(u64 v, float& lo, float& hi) {
    asm("mov.b64 {%0,%1},%2;" : "=f"(lo), "=f"(hi) : "l"(v));
}
__device__ __forceinline__ u64 fma2_(u64 a, u64 b, u64 c) {
    u64 d; asm("fma.rn.f32x2 %0,%1,%2,%3;" : "=l"(d) : "l"(a), "l"(b), "l"(c)); return d;
}
__device__ __forceinline__ u64 mul2_(u64 a, u64 b) {
    u64 d; asm("mul.rn.f32x2 %0,%1,%2;" : "=l"(d) : "l"(a), "l"(b)); return d;
}
__device__ __forceinline__ u64 add2_(u64 a, u64 b) {
    u64 d; asm("add.rn.f32x2 %0,%1,%2;" : "=l"(d) : "l"(a), "l"(b)); return d;
}

// cross-block LN state (zero-init; self-resetting every run)
__device__ float2 g_part[BB * HH];
__device__ int    g_cnt[BB];
__device__ int    g_done[BB];

__global__ void __launch_bounds__(512, 1)
k_fused(const float* __restrict__ query, const float* __restrict__ key_,
        const float* __restrict__ value, const float* __restrict__ wq,
        const float* __restrict__ wk,    const float* __restrict__ wv,
        const float* __restrict__ wf,    const float* __restrict__ lnw,
        const float* __restrict__ lnb,   float* __restrict__ out) {
    const int b    = blockIdx.x >> 4;
    const int h    = blockIdx.x & 15;
    const int tid  = threadIdx.x;
    const int lane = tid & 31;
    const int warp = tid >> 5;

    // ovl: phase1 = staged weights Sq/Sf/Sk/Sv (4 x 2112, pad-132 rows);
    //      phase2 = iv[t*132+p] (2112) reuses the front.
    __shared__ float ovl[8448];
    __shared__ float AshT[256];     // SCALE*A(s,t) at [t*16+s]
    __shared__ float GtsT[256];     // G(t,s)      at [t*16+s]
    __shared__ float Qs[128], Ks[128], Vs[128];
    __shared__ float SAj[NJ * 16];  // [j*16+t]
    __shared__ float AGj[NJ * 16];  // [j*16+t]
    __shared__ float FQ[NJ];        // F_j*QM_j
    __shared__ float Psh[NJ * 16];  // [j*16+t] : U[j][t]*AG[j][t]
    __shared__ float Wfs[NJ];
    __shared__ float redS[4], redS2[4];
    __shared__ float mu_s, rs_s;

    float* Sq = ovl;
    float* Sf = ovl + 2112;
    float* Sk = ovl + 4224;
    float* Sv = ovl + 6336;
    float* iv = ovl;                // overlay after dots

    // ---- per-thread global inputs (issue LDGs early) ----
    float qv = 0.f, kval = 0.f, vval = 0.f, lwv = 0.f, lbv = 0.f;
    if (tid < 128) {
        int gi = b * MM + h * 128 + tid;
        qv = query[gi]; kval = key_[gi]; vval = value[gi];
        lwv = lnw[h * 128 + tid]; lbv = lnb[h * 128 + tid];
    }

    // ---- stage weights: padded rows [st*132 + d], 1 f4 each ----
    {
        int st = tid >> 5, off = tid & 31;
        int fi = st * 33 + off;
        ((float4*)Sq)[fi] = ((const float4*)wq)[tid];
        ((float4*)Sf)[fi] = ((const float4*)wf)[tid];
        ((float4*)Sk)[fi] = ((const float4*)wk)[tid];
        ((float4*)Sv)[fi] = ((const float4*)wv)[tid];
    }
    if (tid < 128) { Qs[tid] = qv; Ks[tid] = kval; Vs[tid] = vval; }
    __syncthreads();

    // ---- dual GEMM 16x16x128 via packed f32x2 FMA ----
    {
        int isG  = warp >> 3;
        int sblk = (warp >> 2) & 1, tblk = warp & 3;
        int s = sblk * 8 + (lane >> 2);
        int t = tblk * 4 + (lane & 3);
        const ulonglong2* X = (const ulonglong2*)((isG ? Sf : Sq) + s * 132);
        const ulonglong2* Y = (const ulonglong2*)((isG ? Sv : Sk) + t * 132);
        u64 a2 = pk2(0.f, 0.f), b2 = a2;
#pragma unroll
        for (int i = 0; i < 32; i++) {
            ulonglong2 x = X[i], y = Y[i];
            a2 = fma2_(x.x, y.x, a2);
            b2 = fma2_(x.y, y.y, b2);
        }
        float lo, hi;
        upk2(add2_(a2, b2), lo, hi);
        float a = lo + hi;
        if (isG) GtsT[t * 16 + s] = a;
        else     AshT[t * 16 + s] = SCALE * a;
    }
    __syncthreads();

    // ---- SA/AG (warps 0-7, serial recurrence) || FQ (warp 8) ----
    if (warp < 8) {
        int t = warp * 2 + (lane >> 4);
        int s = lane & 15;
        float a = AshT[t * 16 + s];
        float g = GtsT[t * 16 + s];
        float pw = 1.f;
#pragma unroll
        for (int j = 0; j < NJ; j++) {
            float sa = pw, ag = pw * g;
            sa += __shfl_xor_sync(0xffffffffu, sa, 1);
            sa += __shfl_xor_sync(0xffffffffu, sa, 2);
            sa += __shfl_xor_sync(0xffffffffu, sa, 4);
            sa += __shfl_xor_sync(0xffffffffu, sa, 8);
            ag += __shfl_xor_sync(0xffffffffu, ag, 1);
            ag += __shfl_xor_sync(0xffffffffu, ag, 2);
            ag += __shfl_xor_sync(0xffffffffu, ag, 4);
            ag += __shfl_xor_sync(0xffffffffu, ag, 8);
            if ((lane & 15) == j) { SAj[j * 16 + t] = sa; AGj[j * 16 + t] = ag; }
            pw *= a;
        }
    } else if (warp == 8) {
        float4 q4 = ((const float4*)Qs)[lane];
        float px = 1.f, py = 1.f, pz = 1.f, pw4 = 1.f;
#pragma unroll
        for (int j = 0; j < NJ; j++) {
            float qm = (px + py) + (pz + pw4);
            qm += __shfl_xor_sync(0xffffffffu, qm, 1);
            qm += __shfl_xor_sync(0xffffffffu, qm, 2);
            qm += __shfl_xor_sync(0xffffffffu, qm, 4);
            qm += __shfl_xor_sync(0xffffffffu, qm, 8);
            qm += __shfl_xor_sync(0xffffffffu, qm, 16);
            if (lane == j) FQ[j] = c_F[j] * qm;
            px *= q4.x; py *= q4.y; pz *= q4.z; pw4 *= q4.w;
        }
    }
    __syncthreads();

    // ---- Z Horner + series reciprocal, packed over t-pairs ----
    {
        int p = tid & 127, tq = tid >> 7;
        float k = Ks[p], v = Vs[p];
        const u64 k2 = pk2(k, k), v2 = pk2(v, v);
        const u64 one2  = pk2(1.f, 1.f);
        const u64 ninv2 = pk2(-INV2048, -INV2048);
        u64 fq2[NJ];
#pragma unroll
        for (int j = 0; j < NJ; j++) { float f = FQ[j]; fq2[j] = pk2(f, f); }
#pragma unroll
        for (int pr = 0; pr < 2; pr++) {
            int t = tq * 4 + pr * 2;                 // pair (t, t+1)
            u64 z2 = mul2_(fq2[NJ - 1], *(const u64*)(SAj + (NJ - 1) * 16 + t));
#pragma unroll
            for (int j = NJ - 2; j >= 0; j--)
                z2 = fma2_(z2, k2, mul2_(fq2[j], *(const u64*)(SAj + j * 16 + t)));
            u64 e2 = fma2_(z2, ninv2, one2);         // -eps  (c0 = 2048 exactly)
            u64 r2 = fma2_(e2, one2, one2);          // 1 - eps
            r2 = fma2_(e2, r2, one2);                // 1 - eps + eps^2
            r2 = fma2_(e2, r2, one2);                // 1 - eps + eps^2 - eps^3
            u64 iv2 = mul2_(v2, r2);                 // V * 2048/Z (1/2048 in Wf)
            float lo, hi; upk2(iv2, lo, hi);
            iv[t * 132 + p]       = lo;
            iv[(t + 1) * 132 + p] = hi;
        }
    }
    __syncthreads();

    // ---- U phase (warp = t): packed partials, serial shfl chain per j ----
    {
        int t = warp;
        float4 iv4 = ((const float4*)(iv + t * 132))[lane];
        float4 k4  = ((const float4*)Ks)[lane];
        u64 iv01 = pk2(iv4.x, iv4.y), iv23 = pk2(iv4.z, iv4.w);
        u64 kk01 = pk2(k4.x,  k4.y),  kk23 = pk2(k4.z,  k4.w);
        u64 k01  = pk2(1.f, 1.f),     k23  = k01;
#pragma unroll
        for (int j = 0; j < NJ; j++) {
            u64 u2 = fma2_(k01, iv01, mul2_(k23, iv23));
            float lo, hi; upk2(u2, lo, hi);
            float u = lo + hi;
            u += __shfl_xor_sync(0xffffffffu, u, 1);
            u += __shfl_xor_sync(0xffffffffu, u, 2);
            u += __shfl_xor_sync(0xffffffffu, u, 4);
            u += __shfl_xor_sync(0xffffffffu, u, 8);
            u += __shfl_xor_sync(0xffffffffu, u, 16);
            if (lane == j) Psh[j * 16 + t] = u * AGj[j * 16 + t];
            k01 = mul2_(k01, kk01);
            k23 = mul2_(k23, kk23);
        }
    }
    __syncthreads();

    // ---- Wf[j] = F_j/2048 * sum_t Psh[j][t] ----
    if (tid < NJ) {
        const float4* p4 = (const float4*)(Psh + tid * 16);
        float4 a = p4[0], c = p4[1], d = p4[2], e = p4[3];
        float s = ((a.x + a.y) + (a.z + a.w)) + ((c.x + c.y) + (c.z + c.w))
                + ((d.x + d.y) + (d.z + d.w)) + ((e.x + e.y) + (e.z + e.w));
        Wfs[tid] = c_F[tid] * INV2048 * s;
    }
    __syncthreads();

    // ---- y = q + sum_j Wf[j] q^j ; per-block LN partials ----
    float yv = 0.f;
    if (tid < 128) {
        float val = Wfs[NJ - 1];
#pragma unroll
        for (int j = NJ - 2; j >= 0; j--) val = fmaf(val, qv, Wfs[j]);
        yv = qv + val;
        float s1 = yv, s2 = yv * yv;
#pragma unroll
        for (int o = 16; o; o >>= 1) {
            s1 += __shfl_down_sync(0xffffffffu, s1, o);
            s2 += __shfl_down_sync(0xffffffffu, s2, o);
        }
        if (lane == 0) { redS[warp] = s1; redS2[warp] = s2; }
    }
    __syncthreads();

    // ---- publish partials, spin until all 16 heads arrived ----
    if (tid == 0) {
        float ps  = (redS[0]  + redS[1])  + (redS[2]  + redS[3]);
        float ps2 = (redS2[0] + redS2[1]) + (redS2[2] + redS2[3]);
        g_part[b * HH + h] = make_float2(ps, ps2);
        __threadfence();
        atomicAdd(&g_cnt[b], 1);
        while (((volatile int*)g_cnt)[b] < HH) { }
        __threadfence();
    }
    __syncthreads();

    // ---- every block computes mu/rs from the 16 partials ----
    if (warp == 0) {
        float a = 0.f, c = 0.f;
        if (lane < HH) {
            float2 pp = __ldcg(&g_part[b * HH + lane]);
            a = pp.x; c = pp.y;
        }
#pragma unroll
        for (int o = 8; o; o >>= 1) {
            a += __shfl_xor_sync(0xffffffffu, a, o);
            c += __shfl_xor_sync(0xffffffffu, c, o);
        }
        if (lane == 0) {
            float mu  = a * (1.0f / MM);
            float var = c * (1.0f / MM) - mu * mu;
            mu_s = mu;
            rs_s = rsqrtf(var + 1e-5f);
        }
    }
    __syncthreads();
    if (tid < 128)
        out[b * MM + h * 128 + tid] = (yv - mu_s) * rs_s * lwv + lbv;

    // ---- reset counters for next graph replay ----
    if (tid == 0) {
        int old = atomicAdd(&g_done[b], 1);
        if (old == HH - 1) { g_cnt[b] = 0; g_done[b] = 0; }
    }
}

extern "C" void kernel_launch(void* const* d_in, const int* in_sizes, int n_in,
                              void* d_out, int out_size) {
    const float* query = (const float*)d_in[0];
    const float* key_  = (const float*)d_in[1];
    const float* value = (const float*)d_in[2];
    const float* wq    = (const float*)d_in[3];
    const float* wk    = (const float*)d_in[4];
    const float* wv    = (const float*)d_in[5];
    const float* wf    = (const float*)d_in[6];
    const float* lw    = (const float*)d_in[7];
    const float* lb    = (const float*)d_in[8];
    float* out = (float*)d_out;

    k_fused<<<BB * HH, 512>>>(query, key_, value, wq, wk, wv, wf, lw, lb, out);
}

// round 17
// speedup vs baseline: 1.1965x; 1.0059x over previous
#include <cuda_runtime.h>
#include <cuda_bf16.h>

#define BB 4
#define MM 2048
#define HH 16
#define NJ 8
#define SCALE   0.3535533905932738f    // (128//16)^-0.5
#define INV2048 4.8828125e-4f          // 1/2048 (exact)

__constant__ float c_F[NJ] = {
    1.0f, 1.0f, 0.5f, 0.16666666666666666f,
    0.041666666666666664f, 0.008333333333333333f,
    0.001388888888888889f, 1.984126984126984e-4f
};

typedef unsigned long long u64;
__device__ __forceinline__ u64 pk2(float lo, float hi) {
    u64 r; asm("mov.b64 %0,{%1,%2};" : "=l"(r) : "f"(lo), "f"(hi)); return r;
}
__device__ __forceinline__ void upk2(u64 v, float& lo, float& hi) {
    asm("mov.b64 {%0,%1},%2;" : "=f"(lo), "=f"(hi) : "l"(v));
}
__device__ __forceinline__ u64 fma2_(u64 a, u64 b, u64 c) {
    u64 d; asm("fma.rn.f32x2 %0,%1,%2,%3;" : "=l"(d) : "l"(a), "l"(b), "l"(c)); return d;
}
__device__ __forceinline__ u64 mul2_(u64 a, u64 b) {
    u64 d; asm("mul.rn.f32x2 %0,%1,%2;" : "=l"(d) : "l"(a), "l"(b)); return d;
}
__device__ __forceinline__ u64 add2_(u64 a, u64 b) {
    u64 d; asm("add.rn.f32x2 %0,%1,%2;" : "=l"(d) : "l"(a), "l"(b)); return d;
}

// cross-block LN state (zero-init; self-resetting every run)
__device__ float2 g_part[BB * HH];
__device__ int    g_cnt[BB];
__device__ int    g_done[BB];

__global__ void __launch_bounds__(512, 1)
k_fused(const float* __restrict__ query, const float* __restrict__ key_,
        const float* __restrict__ value, const float* __restrict__ wq,
        const float* __restrict__ wk,    const float* __restrict__ wv,
        const float* __restrict__ wf,    const float* __restrict__ lnw,
        const float* __restrict__ lnb,   float* __restrict__ out) {
    const int b    = blockIdx.x >> 4;
    const int h    = blockIdx.x & 15;
    const int tid  = threadIdx.x;
    const int lane = tid & 31;
    const int warp = tid >> 5;

    // ovl: phase1 = staged weights Sq/Sf/Sk/Sv (4 x 2112, pad-132 rows);
    //      phase2 = iv[t*132+p] (2112) reuses the front.
    __shared__ float ovl[8448];
    __shared__ float AshT[256];     // SCALE*A(s,t) at [t*16+s]
    __shared__ float GtsT[256];     // G(t,s)      at [t*16+s]
    __shared__ float Qs[128], Ks[128], Vs[128];
    __shared__ float SAj[NJ * 16];  // [j*16+t]
    __shared__ float AGj[NJ * 16];  // [j*16+t]
    __shared__ float FQ[NJ];        // F_j*QM_j
    __shared__ float Psh[NJ * 16];  // [j*16+t] : U[j][t]*AG[j][t]
    __shared__ float Wfs[NJ];
    __shared__ float redS[4], redS2[4];
    __shared__ float mu_s, rs_s;

    float* Sq = ovl;
    float* Sf = ovl + 2112;
    float* Sk = ovl + 4224;
    float* Sv = ovl + 6336;
    float* iv = ovl;                // overlay after dots

    // ---- per-thread global inputs (issue LDGs early) ----
    float qv = 0.f, kval = 0.f, vval = 0.f, lwv = 0.f, lbv = 0.f;
    if (tid < 128) {
        int gi = b * MM + h * 128 + tid;
        qv = query[gi]; kval = key_[gi]; vval = value[gi];
        lwv = lnw[h * 128 + tid]; lbv = lnb[h * 128 + tid];
    }

    // ---- stage weights: padded rows [st*132 + d], 1 f4 each ----
    {
        int st = tid >> 5, off = tid & 31;
        int fi = st * 33 + off;
        ((float4*)Sq)[fi] = ((const float4*)wq)[tid];
        ((float4*)Sf)[fi] = ((const float4*)wf)[tid];
        ((float4*)Sk)[fi] = ((const float4*)wk)[tid];
        ((float4*)Sv)[fi] = ((const float4*)wv)[tid];
    }
    if (tid < 128) { Qs[tid] = qv; Ks[tid] = kval; Vs[tid] = vval; }
    __syncthreads();

    // ---- dual GEMM 16x16x128 via packed f32x2 FMA ----
    {
        int isG  = warp >> 3;
        int sblk = (warp >> 2) & 1, tblk = warp & 3;
        int s = sblk * 8 + (lane >> 2);
        int t = tblk * 4 + (lane & 3);
        const ulonglong2* X = (const ulonglong2*)((isG ? Sf : Sq) + s * 132);
        const ulonglong2* Y = (const ulonglong2*)((isG ? Sv : Sk) + t * 132);
        u64 a2 = pk2(0.f, 0.f), b2 = a2;
#pragma unroll
        for (int i = 0; i < 32; i++) {
            ulonglong2 x = X[i], y = Y[i];
            a2 = fma2_(x.x, y.x, a2);
            b2 = fma2_(x.y, y.y, b2);
        }
        float lo, hi;
        upk2(add2_(a2, b2), lo, hi);
        float a = lo + hi;
        if (isG) GtsT[t * 16 + s] = a;
        else     AshT[t * 16 + s] = SCALE * a;
    }
    __syncthreads();

    // ---- SA/AG (warps 0-7, serial recurrence) || FQ (warp 8) ----
    if (warp < 8) {
        int t = warp * 2 + (lane >> 4);
        int s = lane & 15;
        float a = AshT[t * 16 + s];
        float g = GtsT[t * 16 + s];
        float pw = 1.f;
#pragma unroll
        for (int j = 0; j < NJ; j++) {
            float sa = pw, ag = pw * g;
            sa += __shfl_xor_sync(0xffffffffu, sa, 1);
            sa += __shfl_xor_sync(0xffffffffu, sa, 2);
            sa += __shfl_xor_sync(0xffffffffu, sa, 4);
            sa += __shfl_xor_sync(0xffffffffu, sa, 8);
            ag += __shfl_xor_sync(0xffffffffu, ag, 1);
            ag += __shfl_xor_sync(0xffffffffu, ag, 2);
            ag += __shfl_xor_sync(0xffffffffu, ag, 4);
            ag += __shfl_xor_sync(0xffffffffu, ag, 8);
            if ((lane & 15) == j) { SAj[j * 16 + t] = sa; AGj[j * 16 + t] = ag; }
            pw *= a;
        }
    } else if (warp == 8) {
        float4 q4 = ((const float4*)Qs)[lane];
        float px = 1.f, py = 1.f, pz = 1.f, pw4 = 1.f;
#pragma unroll
        for (int j = 0; j < NJ; j++) {
            float qm = (px + py) + (pz + pw4);
            qm += __shfl_xor_sync(0xffffffffu, qm, 1);
            qm += __shfl_xor_sync(0xffffffffu, qm, 2);
            qm += __shfl_xor_sync(0xffffffffu, qm, 4);
            qm += __shfl_xor_sync(0xffffffffu, qm, 8);
            qm += __shfl_xor_sync(0xffffffffu, qm, 16);
            if (lane == j) FQ[j] = c_F[j] * qm;
            px *= q4.x; py *= q4.y; pz *= q4.z; pw4 *= q4.w;
        }
    }
    __syncthreads();

    // ---- Z Horner + series reciprocal, packed over t-pairs ----
    {
        int p = tid & 127, tq = tid >> 7;
        float k = Ks[p], v = Vs[p];
        const u64 k2 = pk2(k, k), v2 = pk2(v, v);
        const u64 one2  = pk2(1.f, 1.f);
        const u64 ninv2 = pk2(-INV2048, -INV2048);
        u64 fq2[NJ];
#pragma unroll
        for (int j = 0; j < NJ; j++) { float f = FQ[j]; fq2[j] = pk2(f, f); }
#pragma unroll
        for (int pr = 0; pr < 2; pr++) {
            int t = tq * 4 + pr * 2;                 // pair (t, t+1)
            u64 z2 = mul2_(fq2[NJ - 1], *(const u64*)(SAj + (NJ - 1) * 16 + t));
#pragma unroll
            for (int j = NJ - 2; j >= 0; j--)
                z2 = fma2_(z2, k2, mul2_(fq2[j], *(const u64*)(SAj + j * 16 + t)));
            u64 e2 = fma2_(z2, ninv2, one2);         // -eps  (c0 = 2048 exactly)
            u64 r2 = fma2_(e2, one2, one2);          // 1 - eps
            r2 = fma2_(e2, r2, one2);                // 1 - eps + eps^2
            r2 = fma2_(e2, r2, one2);                // 1 - eps + eps^2 - eps^3
            u64 iv2 = mul2_(v2, r2);                 // V * 2048/Z (1/2048 in Wf)
            float lo, hi; upk2(iv2, lo, hi);
            iv[t * 132 + p]       = lo;
            iv[(t + 1) * 132 + p] = hi;
        }
    }
    __syncthreads();

    // ---- U phase (warp = t): packed partials, serial shfl chain per j ----
    {
        int t = warp;
        float4 iv4 = ((const float4*)(iv + t * 132))[lane];
        float4 k4  = ((const float4*)Ks)[lane];
        u64 iv01 = pk2(iv4.x, iv4.y), iv23 = pk2(iv4.z, iv4.w);
        u64 kk01 = pk2(k4.x,  k4.y),  kk23 = pk2(k4.z,  k4.w);
        u64 k01  = pk2(1.f, 1.f),     k23  = k01;
#pragma unroll
        for (int j = 0; j < NJ; j++) {
            u64 u2 = fma2_(k01, iv01, mul2_(k23, iv23));
            float lo, hi; upk2(u2, lo, hi);
            float u = lo + hi;
            u += __shfl_xor_sync(0xffffffffu, u, 1);
            u += __shfl_xor_sync(0xffffffffu, u, 2);
            u += __shfl_xor_sync(0xffffffffu, u, 4);
            u += __shfl_xor_sync(0xffffffffu, u, 8);
            u += __shfl_xor_sync(0xffffffffu, u, 16);
            if (lane == j) Psh[j * 16 + t] = u * AGj[j * 16 + t];
            k01 = mul2_(k01, kk01);
            k23 = mul2_(k23, kk23);
        }
    }
    __syncthreads();

    // ---- Wf[j] = F_j/2048 * sum_t Psh[j][t] ----
    if (tid < NJ) {
        const float4* p4 = (const float4*)(Psh + tid * 16);
        float4 a = p4[0], c = p4[1], d = p4[2], e = p4[3];
        float s = ((a.x + a.y) + (a.z + a.w)) + ((c.x + c.y) + (c.z + c.w))
                + ((d.x + d.y) + (d.z + d.w)) + ((e.x + e.y) + (e.z + e.w));
        Wfs[tid] = c_F[tid] * INV2048 * s;
    }
    __syncthreads();

    // ---- y = q + sum_j Wf[j] q^j ; per-block LN partials ----
    float yv = 0.f;
    if (tid < 128) {
        float val = Wfs[NJ - 1];
#pragma unroll
        for (int j = NJ - 2; j >= 0; j--) val = fmaf(val, qv, Wfs[j]);
        yv = qv + val;
        float s1 = yv, s2 = yv * yv;
#pragma unroll
        for (int o = 16; o; o >>= 1) {
            s1 += __shfl_down_sync(0xffffffffu, s1, o);
            s2 += __shfl_down_sync(0xffffffffu, s2, o);
        }
        if (lane == 0) { redS[warp] = s1; redS2[warp] = s2; }
    }
    __syncthreads();

    // ---- publish partials, spin until all 16 heads arrived ----
    if (tid == 0) {
        float ps  = (redS[0]  + redS[1])  + (redS[2]  + redS[3]);
        float ps2 = (redS2[0] + redS2[1]) + (redS2[2] + redS2[3]);
        g_part[b * HH + h] = make_float2(ps, ps2);
        __threadfence();
        atomicAdd(&g_cnt[b], 1);
        while (((volatile int*)g_cnt)[b] < HH) { }
        __threadfence();
    }
    __syncthreads();

    // ---- every block computes mu/rs from the 16 partials ----
    if (warp == 0) {
        float a = 0.f, c = 0.f;
        if (lane < HH) {
            float2 pp = __ldcg(&g_part[b * HH + lane]);
            a = pp.x; c = pp.y;
        }
#pragma unroll
        for (int o = 8; o; o >>= 1) {
            a += __shfl_xor_sync(0xffffffffu, a, o);
            c += __shfl_xor_sync(0xffffffffu, c, o);
        }
        if (lane == 0) {
            float mu  = a * (1.0f / MM);
            float var = c * (1.0f / MM) - mu * mu;
            mu_s = mu;
            rs_s = rsqrtf(var + 1e-5f);
        }
    }
    __syncthreads();
    if (tid < 128)
        out[b * MM + h * 128 + tid] = (yv - mu_s) * rs_s * lwv + lbv;

    // ---- reset counters for next graph replay ----
    if (tid == 0) {
        int old = atomicAdd(&g_done[b], 1);
        if (old == HH - 1) { g_cnt[b] = 0; g_done[b] = 0; }
    }
}

extern "C" void kernel_launch(void* const* d_in, const int* in_sizes, int n_in,
                              void* d_out, int out_size) {
    const float* query = (const float*)d_in[0];
    const float* key_  = (const float*)d_in[1];
    const float* value = (const float*)d_in[2];
    const float* wq    = (const float*)d_in[3];
    const float* wk    = (const float*)d_in[4];
    const float* wv    = (const float*)d_in[5];
    const float* wf    = (const float*)d_in[6];
    const float* lw    = (const float*)d_in[7];
    const float* lb    = (const float*)d_in[8];
    float* out = (float*)d_out;

    k_fused<<<BB * HH, 512>>>(query, key_, value, wq, wk, wv, wf, lw, lb, out);
}